// round 7
// baseline (speedup 1.0000x reference)
#include <cuda_runtime.h>

#define B_    256
#define N_    8192
#define DK_   128
#define DIN_  512
#define OUTD_ 134
#define NS_   5
#define TILE_ 2048   // elements per k4 block
#define BB_   8      // batches per k1 block

// ---- device scratch ----
__device__ float g_escores[B_ * N_];      // exp(score) (no max shift needed; |score| <~ 6)
__device__ float g_q[B_ * DK_];           // query pre-scaled by 1/sqrt(dk)
__device__ float g_shift[B_ * NS_];       // softmaxed shift distribution
__device__ float g_gate[B_];
__device__ float g_partial[B_ * 256];     // per-block exp sums (deterministic)

__device__ __forceinline__ float warp_sum(float v) {
#pragma unroll
    for (int o = 16; o; o >>= 1) v += __shfl_xor_sync(0xffffffffu, v, o);
    return v;
}

// ---- K1: head GEMM; grid (17, 32), 512 threads ----
// Block (bx, by): outputs [8bx, 8bx+8) x batches [8by, 8by+8).
// Each output row is split across TWO warps (256 DIN-elements each);
// halves combined through smem in fixed order (deterministic).
__global__ void __launch_bounds__(512) k1_head(const float* __restrict__ inp,
                                               const float* __restrict__ W,
                                               const float* __restrict__ bias) {
    __shared__ float s_in[BB_][DIN_];
    __shared__ float s_part[8][BB_][2];
    __shared__ float s_tail[BB_][6];      // args[128..133] per batch (bx==16 only)
    const int tid = threadIdx.x;
    const int warp = tid >> 5, lane = tid & 31;
    const int b0 = blockIdx.y * BB_;

    // load 8 input rows (1024 float4, 512 threads -> 2 each), coalesced
    {
        const float4* ip = reinterpret_cast<const float4*>(inp + (size_t)b0 * DIN_);
        float4* sp = &reinterpret_cast<float4(*)[DIN_ / 4]>(s_in)[0][0];
        sp[tid] = ip[tid];
        sp[tid + 512] = ip[tid + 512];
    }
    __syncthreads();

    const int wo = warp >> 1;             // output slot within block (0..7)
    const int h  = warp & 1;              // DIN half (0..1)
    const int o  = blockIdx.x * 8 + wo;
    if (o < OUTD_) {
        // this warp's half of the W row: columns [h*256, h*256+256)
        const float4* wr = reinterpret_cast<const float4*>(W + (size_t)o * DIN_ + h * 256);
        const float4 w0 = wr[lane], w1 = wr[lane + 32];

        float acc[BB_];
#pragma unroll
        for (int bb = 0; bb < BB_; bb++) {
            const float4* xr = reinterpret_cast<const float4*>(s_in[bb] + h * 256);
            const float4 x0 = xr[lane], x1 = xr[lane + 32];
            float a;
            a = fmaf(w0.x, x0.x, 0.f);
            a = fmaf(w0.y, x0.y, a);
            a = fmaf(w0.z, x0.z, a);
            a = fmaf(w0.w, x0.w, a);
            a = fmaf(w1.x, x1.x, a);
            a = fmaf(w1.y, x1.y, a);
            a = fmaf(w1.z, x1.z, a);
            a = fmaf(w1.w, x1.w, a);
            acc[bb] = a;
        }
#pragma unroll
        for (int bb = 0; bb < BB_; bb++) {
            const float s = warp_sum(acc[bb]);
            if (lane == 0) s_part[wo][bb][h] = s;
        }
    }
    __syncthreads();

    // combine halves: 64 threads, one per (output, batch); fixed order -> deterministic
    if (tid < 64) {
        const int cwo = tid >> 3, bb = tid & 7;
        const int co = blockIdx.x * 8 + cwo;
        if (co < OUTD_) {
            const float s = s_part[cwo][bb][0] + s_part[cwo][bb][1] + bias[co];
            if (co < DK_)
                g_q[(size_t)(b0 + bb) * DK_ + co] = s * 0.088388347648318447f;  // 1/sqrt(128)
            else
                s_tail[bb][co - DK_] = s;
        }
    }
    if (blockIdx.x == 16) {
        __syncthreads();
        if (tid < BB_) {
            const int b = b0 + tid;
            g_gate[b] = 1.f / (1.f + __expf(-s_tail[tid][0]));
            float mx = s_tail[tid][1];
#pragma unroll
            for (int s = 2; s <= NS_; s++) mx = fmaxf(mx, s_tail[tid][s]);
            float e[NS_], sum = 0.f;
#pragma unroll
            for (int s = 0; s < NS_; s++) { e[s] = __expf(s_tail[tid][1 + s] - mx); sum += e[s]; }
            float inv = 1.f / sum;
#pragma unroll
            for (int s = 0; s < NS_; s++) g_shift[b * NS_ + s] = e[s] * inv;
        }
    }
}

// ---- K2: e = exp(memory[b,n,:] . qscaled[b,:]) + deterministic block partial sums ----
// One warp = one 128-float row (32 lanes x float4), 4 rows per warp for MLP=4.
__global__ void k2_scores(const float* __restrict__ mem) {
    __shared__ float s_q[DK_];
    __shared__ float s_ws[8];
    const int b = blockIdx.y, tid = threadIdx.x;
    if (tid < DK_) s_q[tid] = g_q[b * DK_ + tid];
    __syncthreads();
    const int warp = tid >> 5, lane = tid & 31;
    const float4 q4 = reinterpret_cast<float4*>(s_q)[lane];
    const int n0 = blockIdx.x * 32 + warp * 4;
    const float4* mp = reinterpret_cast<const float4*>(mem)
                       + ((size_t)b * N_ + n0) * (DK_ / 4) + lane;
    const float4 m0 = mp[0], m1 = mp[32], m2 = mp[64], m3 = mp[96];
    float d0 = m0.x * q4.x + m0.y * q4.y + m0.z * q4.z + m0.w * q4.w;
    float d1 = m1.x * q4.x + m1.y * q4.y + m1.z * q4.z + m1.w * q4.w;
    float d2 = m2.x * q4.x + m2.y * q4.y + m2.z * q4.z + m2.w * q4.w;
    float d3 = m3.x * q4.x + m3.y * q4.y + m3.z * q4.z + m3.w * q4.w;
    d0 = warp_sum(d0); d1 = warp_sum(d1); d2 = warp_sum(d2); d3 = warp_sum(d3);
    if (lane == 0) {
        const float e0 = __expf(d0), e1 = __expf(d1);
        const float e2 = __expf(d2), e3 = __expf(d3);
        *reinterpret_cast<float4*>(g_escores + (size_t)b * N_ + n0) =
            make_float4(e0, e1, e2, e3);
        s_ws[warp] = (e0 + e1) + (e2 + e3);
    }
    __syncthreads();
    if (tid == 0) {
        float t = 0.f;
#pragma unroll
        for (int w = 0; w < 8; w++) t += s_ws[w];
        g_partial[b * 256 + blockIdx.x] = t;  // fixed order -> deterministic
    }
}

// ---- K4: fused Z-reduce + interp + 5-tap circular shift, 2048 elems/block ----
__global__ void k4_out(const float* __restrict__ prev, float* __restrict__ out) {
    __shared__ float s_int[TILE_ + 8];
    __shared__ float s_sh[NS_];
    __shared__ float s_red[8];
    __shared__ float s_c[2];
    const int b = blockIdx.y, tid = threadIdx.x;
    const int warp = tid >> 5, lane = tid & 31;
    const int base = blockIdx.x * TILE_;

    float p = g_partial[b * 256 + tid];
    p = warp_sum(p);
    if (lane == 0) s_red[warp] = p;
    if (tid < NS_) s_sh[tid] = g_shift[b * NS_ + tid];
    __syncthreads();
    if (tid == 0) {
        float Z = 0.f;
#pragma unroll
        for (int w = 0; w < 8; w++) Z += s_red[w];
        const float g = g_gate[b];
        s_c[0] = g / Z;
        s_c[1] = 1.f - g;
    }
    __syncthreads();
    const float cA = s_c[0], cB = s_c[1];

    const float4* ep = reinterpret_cast<const float4*>(g_escores + (size_t)b * N_ + base);
    const float4* pp = reinterpret_cast<const float4*>(prev + (size_t)b * N_ + base);
#pragma unroll
    for (int i = 0; i < TILE_ / 1024; i++) {
        const int v = tid + i * 256;
        const float4 e = ep[v], pr = pp[v];
        float4 r;
        r.x = cA * e.x + cB * pr.x;
        r.y = cA * e.y + cB * pr.y;
        r.z = cA * e.z + cB * pr.z;
        r.w = cA * e.w + cB * pr.w;
        *reinterpret_cast<float4*>(s_int + 4 + v * 4) = r;
    }
    if (tid < 4) {
        const int k = (tid < 2) ? (tid - 2) : (TILE_ + tid - 2);
        const int n = (base + k + N_) & (N_ - 1);
        const size_t idx = (size_t)b * N_ + n;
        s_int[4 + k] = cA * g_escores[idx] + cB * prev[idx];
    }
    __syncthreads();

    const float sh0 = s_sh[0], sh1 = s_sh[1], sh2 = s_sh[2], sh3 = s_sh[3], sh4 = s_sh[4];
    float4* op = reinterpret_cast<float4*>(out + (size_t)b * N_ + base);
    const float4* si4 = reinterpret_cast<const float4*>(s_int);
#pragma unroll
    for (int i = 0; i < TILE_ / 1024; i++) {
        const int v = tid + i * 256;
        const float4 f0 = si4[v];
        const float4 f1 = si4[v + 1];
        const float4 f2 = si4[v + 2];
        float4 o;
        o.x = sh0 * f0.z + sh1 * f0.w + sh2 * f1.x + sh3 * f1.y + sh4 * f1.z;
        o.y = sh0 * f0.w + sh1 * f1.x + sh2 * f1.y + sh3 * f1.z + sh4 * f1.w;
        o.z = sh0 * f1.x + sh1 * f1.y + sh2 * f1.z + sh3 * f1.w + sh4 * f2.x;
        o.w = sh0 * f1.y + sh1 * f1.z + sh2 * f1.w + sh3 * f2.x + sh4 * f2.y;
        op[v] = o;
    }
}

extern "C" void kernel_launch(void* const* d_in, const int* in_sizes, int n_in,
                              void* d_out, int out_size) {
    const float* inp  = (const float*)d_in[0];
    const float* mem  = (const float*)d_in[1];
    const float* prev = (const float*)d_in[2];
    const float* W    = (const float*)d_in[3];
    const float* bias = (const float*)d_in[4];
    float* out = (float*)d_out;

    k1_head<<<dim3(17, B_ / BB_), 512>>>(inp, W, bias);
    k2_scores<<<dim3(N_ / 32, B_), 256>>>(mem);
    k4_out<<<dim3(N_ / TILE_, B_), 256>>>(prev, out);
}

// round 8
// speedup vs baseline: 1.0017x; 1.0017x over previous
#include <cuda_runtime.h>

#define B_    256
#define N_    8192
#define DK_   128
#define DIN_  512
#define OUTD_ 134
#define NS_   5
#define TILE_ 2048   // elements per k4 block
#define BB_   8      // batches per k1 block
#define KP_   128    // k2 blocks per batch (N/64)

// ---- device scratch ----
__device__ float g_escores[B_ * N_];      // exp(score) (no max shift needed; |score| <~ 6)
__device__ float g_q[B_ * DK_];           // query pre-scaled by 1/sqrt(dk)
__device__ float g_shift[B_ * NS_];       // softmaxed shift distribution
__device__ float g_gate[B_];
__device__ float g_partial[B_ * KP_];     // per-block exp sums (deterministic)

__device__ __forceinline__ float warp_sum(float v) {
#pragma unroll
    for (int o = 16; o; o >>= 1) v += __shfl_xor_sync(0xffffffffu, v, o);
    return v;
}

// ---- K1: head GEMM with 8-batch W reuse; grid (17, 32), 256 threads (R6 shape) ----
__global__ void k1_head(const float* __restrict__ inp,
                        const float* __restrict__ W,
                        const float* __restrict__ bias) {
    __shared__ float s_in[BB_][DIN_];
    __shared__ float s_tail[BB_][6];      // args[128..133] per batch (bx==16 only)
    const int tid = threadIdx.x;
    const int warp = tid >> 5, lane = tid & 31;
    const int b0 = blockIdx.y * BB_;

    {
        const float4* ip = reinterpret_cast<const float4*>(inp + (size_t)b0 * DIN_);
        float4* sp = &reinterpret_cast<float4(*)[DIN_ / 4]>(s_in)[0][0];
#pragma unroll
        for (int i = 0; i < 4; i++) sp[tid + i * 256] = ip[tid + i * 256];
    }
    __syncthreads();

    const int o = blockIdx.x * 8 + warp;
    if (o < OUTD_) {
        const float4* wr = reinterpret_cast<const float4*>(W + (size_t)o * DIN_);
        float4 w[4];
#pragma unroll
        for (int j = 0; j < 4; j++) w[j] = wr[lane + 32 * j];

        float acc[BB_];
#pragma unroll
        for (int bb = 0; bb < BB_; bb++) acc[bb] = 0.f;
#pragma unroll
        for (int j = 0; j < 4; j++) {
#pragma unroll
            for (int bb = 0; bb < BB_; bb++) {
                const float4 x = reinterpret_cast<const float4*>(s_in[bb])[lane + 32 * j];
                acc[bb] = fmaf(w[j].x, x.x,
                           fmaf(w[j].y, x.y,
                            fmaf(w[j].z, x.z,
                             fmaf(w[j].w, x.w, acc[bb]))));
            }
        }
        const float bo = bias[o];
#pragma unroll
        for (int bb = 0; bb < BB_; bb++) {
            float s = warp_sum(acc[bb]);
            if (lane == 0) {
                s += bo;
                if (o < DK_)
                    g_q[(size_t)(b0 + bb) * DK_ + o] = s * 0.088388347648318447f;
                else
                    s_tail[bb][o - DK_] = s;
            }
        }
    }
    if (blockIdx.x == 16) {
        __syncthreads();
        if (tid < BB_) {
            const int b = b0 + tid;
            g_gate[b] = 1.f / (1.f + __expf(-s_tail[tid][0]));
            float mx = s_tail[tid][1];
#pragma unroll
            for (int s = 2; s <= NS_; s++) mx = fmaxf(mx, s_tail[tid][s]);
            float e[NS_], sum = 0.f;
#pragma unroll
            for (int s = 0; s < NS_; s++) { e[s] = __expf(s_tail[tid][1 + s] - mx); sum += e[s]; }
            float inv = 1.f / sum;
#pragma unroll
            for (int s = 0; s < NS_; s++) g_shift[b * NS_ + s] = e[s] * inv;
        }
    }
}

// ---- K2: e = exp(memory[b,n,:] . q[b,:]) ; 8 rows/warp (MLP=8), 64 rows/block ----
__global__ void k2_scores(const float* __restrict__ mem) {
    __shared__ float s_q[DK_];
    __shared__ float s_ws[8];
    const int b = blockIdx.y, tid = threadIdx.x;
    if (tid < DK_) s_q[tid] = g_q[b * DK_ + tid];
    __syncthreads();
    const int warp = tid >> 5, lane = tid & 31;
    const float4 q4 = reinterpret_cast<float4*>(s_q)[lane];
    const int n0 = blockIdx.x * 64 + warp * 8;
    const float4* mp = reinterpret_cast<const float4*>(mem)
                       + ((size_t)b * N_ + n0) * (DK_ / 4) + lane;
    // 8 independent row loads in flight (front-batched -> MLP=8)
    float4 m[8];
#pragma unroll
    for (int r = 0; r < 8; r++) m[r] = mp[32 * r];
    float d[8];
#pragma unroll
    for (int r = 0; r < 8; r++)
        d[r] = m[r].x * q4.x + m[r].y * q4.y + m[r].z * q4.z + m[r].w * q4.w;
#pragma unroll
    for (int r = 0; r < 8; r++) d[r] = warp_sum(d[r]);
    if (lane == 0) {
        float e[8];
#pragma unroll
        for (int r = 0; r < 8; r++) e[r] = __expf(d[r]);
        float* sc = g_escores + (size_t)b * N_ + n0;
        *reinterpret_cast<float4*>(sc)     = make_float4(e[0], e[1], e[2], e[3]);
        *reinterpret_cast<float4*>(sc + 4) = make_float4(e[4], e[5], e[6], e[7]);
        float t = 0.f;
#pragma unroll
        for (int r = 0; r < 8; r++) t += e[r];
        s_ws[warp] = t;
    }
    __syncthreads();
    if (tid == 0) {
        float t = 0.f;
#pragma unroll
        for (int w = 0; w < 8; w++) t += s_ws[w];
        g_partial[b * KP_ + blockIdx.x] = t;  // fixed order -> deterministic
    }
}

// ---- K4: fused Z-reduce + interp + 5-tap circular shift, 2048 elems/block ----
__global__ void k4_out(const float* __restrict__ prev, float* __restrict__ out) {
    __shared__ float s_int[TILE_ + 8];
    __shared__ float s_sh[NS_];
    __shared__ float s_red[4];
    __shared__ float s_c[2];
    const int b = blockIdx.y, tid = threadIdx.x;
    const int warp = tid >> 5, lane = tid & 31;
    const int base = blockIdx.x * TILE_;

    // deterministic Z reduce over 128 partials (warps 0..3)
    float p = (tid < KP_) ? g_partial[b * KP_ + tid] : 0.f;
    p = warp_sum(p);
    if (lane == 0 && warp < 4) s_red[warp] = p;
    if (tid < NS_) s_sh[tid] = g_shift[b * NS_ + tid];
    __syncthreads();
    if (tid == 0) {
        const float Z = (s_red[0] + s_red[1]) + (s_red[2] + s_red[3]);
        const float g = g_gate[b];
        s_c[0] = g / Z;
        s_c[1] = 1.f - g;
    }
    __syncthreads();
    const float cA = s_c[0], cB = s_c[1];

    const float4* ep = reinterpret_cast<const float4*>(g_escores + (size_t)b * N_ + base);
    const float4* pp = reinterpret_cast<const float4*>(prev + (size_t)b * N_ + base);
#pragma unroll
    for (int i = 0; i < TILE_ / 1024; i++) {
        const int v = tid + i * 256;
        const float4 e = ep[v], pr = pp[v];
        float4 r;
        r.x = cA * e.x + cB * pr.x;
        r.y = cA * e.y + cB * pr.y;
        r.z = cA * e.z + cB * pr.z;
        r.w = cA * e.w + cB * pr.w;
        *reinterpret_cast<float4*>(s_int + 4 + v * 4) = r;
    }
    if (tid < 4) {
        const int k = (tid < 2) ? (tid - 2) : (TILE_ + tid - 2);
        const int n = (base + k + N_) & (N_ - 1);
        const size_t idx = (size_t)b * N_ + n;
        s_int[4 + k] = cA * g_escores[idx] + cB * prev[idx];
    }
    __syncthreads();

    const float sh0 = s_sh[0], sh1 = s_sh[1], sh2 = s_sh[2], sh3 = s_sh[3], sh4 = s_sh[4];
    float4* op = reinterpret_cast<float4*>(out + (size_t)b * N_ + base);
    const float4* si4 = reinterpret_cast<const float4*>(s_int);
#pragma unroll
    for (int i = 0; i < TILE_ / 1024; i++) {
        const int v = tid + i * 256;
        const float4 f0 = si4[v];
        const float4 f1 = si4[v + 1];
        const float4 f2 = si4[v + 2];
        float4 o;
        o.x = sh0 * f0.z + sh1 * f0.w + sh2 * f1.x + sh3 * f1.y + sh4 * f1.z;
        o.y = sh0 * f0.w + sh1 * f1.x + sh2 * f1.y + sh3 * f1.z + sh4 * f1.w;
        o.z = sh0 * f1.x + sh1 * f1.y + sh2 * f1.z + sh3 * f1.w + sh4 * f2.x;
        o.w = sh0 * f1.y + sh1 * f1.z + sh2 * f1.w + sh3 * f2.x + sh4 * f2.y;
        op[v] = o;
    }
}

extern "C" void kernel_launch(void* const* d_in, const int* in_sizes, int n_in,
                              void* d_out, int out_size) {
    const float* inp  = (const float*)d_in[0];
    const float* mem  = (const float*)d_in[1];
    const float* prev = (const float*)d_in[2];
    const float* W    = (const float*)d_in[3];
    const float* bias = (const float*)d_in[4];
    float* out = (float*)d_out;

    k1_head<<<dim3(17, B_ / BB_), 256>>>(inp, W, bias);
    k2_scores<<<dim3(KP_, B_), 256>>>(mem);
    k4_out<<<dim3(N_ / TILE_, B_), 256>>>(prev, out);
}